// round 15
// baseline (speedup 1.0000x reference)
#include <cuda_runtime.h>
#include <cstdint>
#include <cstddef>

#define NL  6
#define HN  256
#define GN  1024
#define IND 128
#define BN  128
#define TN  512
#define ON  10
#define CL  8

typedef unsigned long long ull;

// ---------------- scratch (static device globals: allowed) ----------------
__device__ float g_gx[(size_t)BN * TN * GN];        // 256 MB: per-layer input-GEMM result
__device__ float g_act[2][(size_t)BN * TN * HN];    // 2 x 64 MB: layer activations ping-pong

// ---------------- helpers ----------------
__device__ __forceinline__ ull fma2(ull a, ull b, ull c) {
    ull d;
    asm("fma.rn.f32x2 %0, %1, %2, %3;" : "=l"(d) : "l"(a), "l"(b), "l"(c));
    return d;
}
__device__ __forceinline__ float lo_f(ull v){ return __uint_as_float((unsigned)(v & 0xffffffffull)); }
__device__ __forceinline__ float hi_f(ull v){ return __uint_as_float((unsigned)(v >> 32)); }

__device__ __forceinline__ float sigm(float x){ return 1.f / (1.f + __expf(-x)); }
__device__ __forceinline__ float tanh_f(float x){
    float ax = fabsf(x);
    float e  = __expf(2.f * ax);          // inf-safe: 2/inf -> 0 -> r=1
    float r  = 1.f - 2.f / (e + 1.f);
    return copysignf(r, x);
}
__device__ __forceinline__ unsigned cluster_rank(){
    unsigned r; asm("mov.u32 %0, %%cluster_ctarank;" : "=r"(r)); return r;
}
__device__ __forceinline__ unsigned mapa_u32(unsigned a, unsigned r){
    unsigned d; asm("mapa.shared::cluster.u32 %0, %1, %2;" : "=r"(d) : "r"(a), "r"(r)); return d;
}
__device__ __forceinline__ unsigned smem_u32(const void* p){
    return (unsigned)__cvta_generic_to_shared(p);
}
__device__ __forceinline__ void cpa16(unsigned dst, const float* src){
    asm volatile("cp.async.cg.shared.global [%0], [%1], 16;" :: "r"(dst), "l"(src) : "memory");
}

// ---------------- input GEMM: gx[m][n] = sum_k A[m][k]*Wih[n][k] + (bih[n]+bhh[n]) ----------------
__global__ void __launch_bounds__(256) gx_gemm(
    const float* __restrict__ Aext, int inIdx, int lda, int K,
    const float* __restrict__ W,              // [GN][HN] row stride HN always
    const float* __restrict__ bih, const float* __restrict__ bhh)
{
    const float* A = Aext ? Aext : g_act[inIdx];
    __shared__ ull As[128 * 9];               // 128 rows x 8 k-pairs, padded to 9
    __shared__ ull Bs[64 * 9];

    const int tid = threadIdx.x;
    const int m0 = blockIdx.x * 128;
    const int n0 = blockIdx.y * 64;
    const int tx = tid & 15;                  // n group
    const int ty = tid >> 4;                  // m group

    ull acc[8][4] = {};

    const int nchunk = K >> 4;
    for (int kb = 0; kb < nchunk; kb++) {
        {   // load A tile: 128 rows x 16 floats (8 ull). 2 threads/row, 4 ull each.
            int row  = tid >> 1;
            const float* ga = A + (size_t)(m0 + row) * lda + kb * 16 + (tid & 1) * 8;
            ull* dst = &As[row * 9 + (tid & 1) * 4];
            #pragma unroll
            for (int q = 0; q < 4; q++) dst[q] = *(const ull*)(ga + q * 2);
        }
        if (tid < 128) {  // load W tile: 64 rows x 16 floats
            int rw = tid >> 1;
            const float* gb = W + (size_t)(n0 + rw) * HN + kb * 16 + (tid & 1) * 8;
            ull* db = &Bs[rw * 9 + (tid & 1) * 4];
            #pragma unroll
            for (int q = 0; q < 4; q++) db[q] = *(const ull*)(gb + q * 2);
        }
        __syncthreads();

        #pragma unroll
        for (int kp = 0; kp < 8; kp++) {
            ull b2[4];
            #pragma unroll
            for (int j = 0; j < 4; j++) b2[j] = Bs[(tx + 16 * j) * 9 + kp];
            #pragma unroll
            for (int i = 0; i < 8; i++) {
                ull a2 = As[(ty + 16 * i) * 9 + kp];
                #pragma unroll
                for (int j = 0; j < 4; j++) acc[i][j] = fma2(a2, b2[j], acc[i][j]);
            }
        }
        __syncthreads();
    }

    #pragma unroll
    for (int j = 0; j < 4; j++) {
        int n = n0 + tx + 16 * j;
        float bias = bih[n] + bhh[n];
        #pragma unroll
        for (int i = 0; i < 8; i++) {
            int m = m0 + ty + 16 * i;
            g_gx[(size_t)m * GN + n] = lo_f(acc[i][j]) + hi_f(acc[i][j]) + bias;
        }
    }
}

// ---------------- recurrent scan (one launch per layer) ----------------
// 16 clusters x 8 CTAs, 512 threads/CTA. Cluster c owns batch rows [8c,8c+8).
// CTA rank r owns hidden units [32r,32r+32) -> 128 gate rows of W_hh held
// ENTIRELY IN REGISTERS: thread (g2 = tid&63, kq = tid>>6) keeps gate rows
// {2g2, 2g2+1}, K-slice [32kq, 32kq+32) = 64 registers of weights.
// Per step:
//   - warps 0-7: vectorized 16B cp.async.cg prefetch of gx(t) into gxs[t&1]
//   - mbarrier wait (count 64, phase parity): all peers' h(t-1) arrived
//   - matvec: register weights x broadcast-LDS h -> pre[t&1] (double buffered)
//   - __syncthreads (only sync in the loop)
//   - stage2 (warps 0-7): reduce partials + gx, activations, c/h update; h pairs
//     to all 8 CTAs via st.shared::cluster.b64; per-warp-leader
//     mbarrier.arrive.RELEASE.cluster at every CTA (no separate cluster fence).
//   - no trailing sync: warps 8-15 run ahead into step t+1's matvec, overlapping
//     the DSMEM exchange tail. Buffer reuse is ordered by sync#1/phase edges.
#define SCAN_H_F   4096                       // hbuf [2][8][256]
#define SCAN_P_F   16384                      // pre  [2][8 kq][8 row][128 gr]
#define SCAN_G_F   2048                       // gxs  [2][8 row][4 q][32 u]
#define SCAN_C_F   256                        // cst
#define SCAN_SMEM_FLOATS (SCAN_H_F + SCAN_P_F + SCAN_G_F + SCAN_C_F + 8)
#define SCAN_SMEM_BYTES  (SCAN_SMEM_FLOATS * 4)

__global__ void __cluster_dims__(CL, 1, 1) __launch_bounds__(512, 1)
lstm_scan(const float* __restrict__ whh,   // [GN][HN] for this layer
          const float* __restrict__ h0l,   // [BN][HN]
          const float* __restrict__ c0l,   // [BN][HN]
          int outIdx)
{
    extern __shared__ float sm[];
    float* hbuf = sm;                                   // [2][8][256]
    float* pre  = hbuf + SCAN_H_F;                      // [2][8][8][128]
    float* gxs  = pre + SCAN_P_F;                       // [2][8][4][32]
    float* cst  = gxs + SCAN_G_F;                       // [256]
    const unsigned mbar = smem_u32(cst + SCAN_C_F);     // 8B aligned
    const unsigned hbase = smem_u32(hbuf);
    const unsigned gxbase = smem_u32(gxs);

    const int tid   = threadIdx.x;
    const unsigned rank = cluster_rank();   // 0..7
    const int bb    = (blockIdx.x >> 3) * 8;            // first batch row

    const int g2  = tid & 63;               // gate-row pair
    const int kq  = tid >> 6;               // 0..7, warp-uniform
    const int row = tid >> 5, u = tid & 31; // stage-2 mapping (tid<256)
    const int gu  = rank * 32 + u;
    // gx loader mapping (tid<256): 16B chunk per thread
    const int lrow = tid >> 5, lq = (tid >> 3) & 3, lseg = tid & 7;

    // ---- init mbarrier (count = 8 warps x 8 CTAs = 64 arrivals per step)
    if (tid == 0)
        asm volatile("mbarrier.init.shared.b64 [%0], %1;" :: "r"(mbar), "r"(64) : "memory");

    // ---- load this thread's W slice into REGISTERS (loop-invariant)
    ulonglong2 W0[8], W1[8];
    {
        int gr0 = 2 * g2,     q0 = gr0 >> 5, ul0 = gr0 & 31;
        int gr1 = 2 * g2 + 1, q1 = gr1 >> 5, ul1 = gr1 & 31;
        const float* w0p = whh + (size_t)(q0 * HN + rank * 32 + ul0) * HN + kq * 32;
        const float* w1p = whh + (size_t)(q1 * HN + rank * 32 + ul1) * HN + kq * 32;
        #pragma unroll
        for (int kk = 0; kk < 8; kk++) {
            W0[kk] = *(const ulonglong2*)(w0p + kk * 4);
            W1[kk] = *(const ulonglong2*)(w1p + kk * 4);
        }
    }

    // ---- init h (buffer 0), c
    for (int li = tid; li < 8 * HN; li += 512)
        hbuf[li] = h0l[(size_t)(bb + (li >> 8)) * HN + (li & 255)];
    if (tid < 256)
        cst[tid] = c0l[(size_t)(bb + row) * HN + gu];
    __syncthreads();
    // cluster sync: all mbarriers initialized before any remote arrive can land
    asm volatile("barrier.cluster.arrive.aligned;" ::: "memory");
    asm volatile("barrier.cluster.wait.aligned;"   ::: "memory");

    float* seq_out = g_act[outIdx];
    int ph = 0;                             // mbarrier phase parity

    for (int t = 0; t < TN; t++) {
        const int cur = t & 1, nxt = cur ^ 1;
        const int pb  = t & 1;              // pre/gxs buffer for this step

        // ---- prefetch gx(t): 256 x 16B cp.async.cg (warps 0-7 only)
        if (tid < 256) {
            const float* g = g_gx + ((size_t)(bb + lrow) * TN + t) * GN
                           + lq * HN + rank * 32 + lseg * 4;
            unsigned d = gxbase + (unsigned)((pb * 1024 + lrow * 128 + lq * 32 + lseg * 4) * 4);
            cpa16(d, g);
            asm volatile("cp.async.commit_group;" ::: "memory");
        }

        // ---- wait for all peers' h(t-1) (64 arrivals); acquire cluster scope
        if (t) {
            unsigned done = 0;
            do {
                asm volatile(
                    "{\n\t.reg .pred P;\n\t"
                    "mbarrier.try_wait.parity.acquire.cluster.shared::cta.b64 P, [%1], %2, 0x989680;\n\t"
                    "selp.b32 %0, 1, 0, P;\n\t}"
                    : "=r"(done) : "r"(mbar), "r"(ph) : "memory");
            } while (!done);
            ph ^= 1;
        }

        // ---- matvec: register weights, broadcast h; two 4-row passes
        {
            const ulonglong2* hb = (const ulonglong2*)(hbuf + cur * 2048) + kq * 8;
            float* prw = pre + pb * 8192;
            #pragma unroll
            for (int pass = 0; pass < 2; pass++) {
                ull a0[4] = {}, a1[4] = {};
                const ulonglong2* hp = hb + pass * 4 * 64;
                #pragma unroll
                for (int kk = 0; kk < 8; kk++) {
                    ulonglong2 w0 = W0[kk], w1 = W1[kk];
                    #pragma unroll
                    for (int r = 0; r < 4; r++) {
                        ulonglong2 h = hp[r * 64 + kk];   // warp-uniform broadcast
                        a0[r] = fma2(w0.x, h.x, a0[r]);
                        a0[r] = fma2(w0.y, h.y, a0[r]);
                        a1[r] = fma2(w1.x, h.x, a1[r]);
                        a1[r] = fma2(w1.y, h.y, a1[r]);
                    }
                }
                #pragma unroll
                for (int r = 0; r < 4; r++) {
                    float p0 = lo_f(a0[r]) + hi_f(a0[r]);
                    float p1 = lo_f(a1[r]) + hi_f(a1[r]);
                    ull pk = ((ull)__float_as_uint(p1) << 32) | (ull)__float_as_uint(p0);
                    *(ull*)&prw[(kq * 8 + pass * 4 + r) * 128 + 2 * g2] = pk;  // STS.64
                }
            }
        }
        __syncthreads();   // partials complete; the ONLY intra-step CTA sync

        // ---- stage 2: reduce partials + activations + state + DSMEM broadcast
        if (tid < 256) {
            asm volatile("cp.async.wait_group 0;" ::: "memory");
            const float* gxr = gxs + pb * 1024 + row * 128;
            float gi = gxr[u], gf = gxr[32 + u], gg = gxr[64 + u], go = gxr[96 + u];
            const float* prr = pre + pb * 8192;
            #pragma unroll
            for (int p = 0; p < 8; p++) {
                const float* pr = prr + (p * 8 + row) * 128;
                gi += pr[u];
                gf += pr[32 + u];
                gg += pr[64 + u];
                go += pr[96 + u];
            }

            float c = sigm(gf) * cst[tid] + sigm(gi) * tanh_f(gg);
            float h = sigm(go) * tanh_f(c);

            // pack (h_u, h_{u+1}) in even lanes: one b64 remote store per CTA
            float hup = __shfl_down_sync(0xffffffffu, h, 1);
            if ((tid & 1) == 0) {
                ull hv = ((ull)__float_as_uint(hup) << 32) | (ull)__float_as_uint(h);
                unsigned off = (unsigned)((nxt * 2048 + row * HN + gu) * 4);
                #pragma unroll
                for (int d = 0; d < CL; d++) {
                    unsigned ra = mapa_u32(hbase, (unsigned)d) + off;
                    asm volatile("st.shared::cluster.b64 [%0], %1;"
                                 :: "r"(ra), "l"(hv) : "memory");
                }
            }
            __syncwarp();     // orders all lanes' stores before the leader's release-arrive
            if ((tid & 31) == 0) {
                #pragma unroll
                for (int d = 0; d < CL; d++) {
                    unsigned rb = mapa_u32(mbar, (unsigned)d);
                    asm volatile("mbarrier.arrive.release.cluster.shared::cluster.b64 _, [%0];"
                                 :: "r"(rb) : "memory");
                }
            }
            // off the cluster critical path:
            cst[tid] = c;
            seq_out[((size_t)(bb + row) * TN + t) * HN + gu] = h;
        }
        // no trailing syncthreads: warps 8-15 run ahead into step t+1
    }

    // exit safety: no CTA may leave while peers' remote stores could be in flight
    asm volatile("barrier.cluster.arrive.aligned;" ::: "memory");
    asm volatile("barrier.cluster.wait.aligned;"   ::: "memory");
}

// ---------------- final FC: out[b][o] = h_last[b] . fc_w[o] + fc_b[o] ----------------
__global__ void __launch_bounds__(256) fc_kernel(
    const float* __restrict__ fcw, const float* __restrict__ fcb,
    float* __restrict__ out)
{
    __shared__ float hs[HN];
    int b = blockIdx.x;
    const float* h = &g_act[(NL - 1) & 1][((size_t)b * TN + (TN - 1)) * HN];
    hs[threadIdx.x] = h[threadIdx.x];
    __syncthreads();
    if (threadIdx.x < ON) {
        int o = threadIdx.x;
        float s = fcb[o];
        #pragma unroll 8
        for (int u = 0; u < HN; u++) s += hs[u] * fcw[o * HN + u];
        out[b * ON + o] = s;
    }
}

// ---------------- launch ----------------
extern "C" void kernel_launch(void* const* d_in, const int* in_sizes, int n_in,
                              void* d_out, int out_size)
{
    (void)in_sizes; (void)n_in; (void)out_size;
    const float* x   = (const float*)d_in[0];
    const float* h0  = (const float*)d_in[1];
    const float* c0  = (const float*)d_in[2];
    const float* wih = (const float*)d_in[3];
    const float* whh = (const float*)d_in[4];
    const float* bih = (const float*)d_in[5];
    const float* bhh = (const float*)d_in[6];
    const float* fcw = (const float*)d_in[7];
    const float* fcb = (const float*)d_in[8];
    float* out = (float*)d_out;

    // idempotent, host-side, capture-safe
    cudaFuncSetAttribute(lstm_scan, cudaFuncAttributeMaxDynamicSharedMemorySize, SCAN_SMEM_BYTES);

    for (int l = 0; l < NL; l++) {
        const float* A = (l == 0) ? x : nullptr;
        int inIdx = (l == 0) ? 0 : ((l - 1) & 1);
        int lda   = (l == 0) ? IND : HN;
        dim3 grid(BN * TN / 128, GN / 64);
        gx_gemm<<<grid, 256>>>(A, inIdx, lda, lda,
                               wih + (size_t)l * GN * HN,
                               bih + (size_t)l * GN,
                               bhh + (size_t)l * GN);
        lstm_scan<<<128, 512, SCAN_SMEM_BYTES>>>(
            whh + (size_t)l * GN * HN,
            h0  + (size_t)l * BN * HN,
            c0  + (size_t)l * BN * HN,
            l & 1);
    }
    fc_kernel<<<BN, 256>>>(fcw, fcb, out);
}

// round 16
// speedup vs baseline: 1.2904x; 1.2904x over previous
#include <cuda_runtime.h>
#include <cstdint>
#include <cstddef>

#define NL  6
#define HN  256
#define GN  1024
#define IND 128
#define BN  128
#define TN  512
#define ON  10
#define CL  8

typedef unsigned long long ull;

// ---------------- scratch (static device globals: allowed) ----------------
__device__ float g_gx[(size_t)BN * TN * GN];        // 256 MB: per-layer input-GEMM result
__device__ float g_act[2][(size_t)BN * TN * HN];    // 2 x 64 MB: layer activations ping-pong

// ---------------- helpers ----------------
__device__ __forceinline__ ull fma2(ull a, ull b, ull c) {
    ull d;
    asm("fma.rn.f32x2 %0, %1, %2, %3;" : "=l"(d) : "l"(a), "l"(b), "l"(c));
    return d;
}
__device__ __forceinline__ float lo_f(ull v){ return __uint_as_float((unsigned)(v & 0xffffffffull)); }
__device__ __forceinline__ float hi_f(ull v){ return __uint_as_float((unsigned)(v >> 32)); }

__device__ __forceinline__ float sigm(float x){ return 1.f / (1.f + __expf(-x)); }
__device__ __forceinline__ float tanh_f(float x){
    float ax = fabsf(x);
    float e  = __expf(2.f * ax);          // inf-safe: 2/inf -> 0 -> r=1
    float r  = 1.f - 2.f / (e + 1.f);
    return copysignf(r, x);
}
__device__ __forceinline__ unsigned cluster_rank(){
    unsigned r; asm("mov.u32 %0, %%cluster_ctarank;" : "=r"(r)); return r;
}
__device__ __forceinline__ unsigned mapa_u32(unsigned a, unsigned r){
    unsigned d; asm("mapa.shared::cluster.u32 %0, %1, %2;" : "=r"(d) : "r"(a), "r"(r)); return d;
}
__device__ __forceinline__ unsigned smem_u32(const void* p){
    return (unsigned)__cvta_generic_to_shared(p);
}
__device__ __forceinline__ void cpa16(unsigned dst, const float* src){
    asm volatile("cp.async.cg.shared.global [%0], [%1], 16;" :: "r"(dst), "l"(src) : "memory");
}

// ---------------- input GEMM: gx[m][n] = sum_k A[m][k]*Wih[n][k] + (bih[n]+bhh[n]) ----------------
__global__ void __launch_bounds__(256) gx_gemm(
    const float* __restrict__ Aext, int inIdx, int lda, int K,
    const float* __restrict__ W,              // [GN][HN] row stride HN always
    const float* __restrict__ bih, const float* __restrict__ bhh)
{
    const float* A = Aext ? Aext : g_act[inIdx];
    __shared__ ull As[128 * 9];               // 128 rows x 8 k-pairs, padded to 9
    __shared__ ull Bs[64 * 9];

    const int tid = threadIdx.x;
    const int m0 = blockIdx.x * 128;
    const int n0 = blockIdx.y * 64;
    const int tx = tid & 15;                  // n group
    const int ty = tid >> 4;                  // m group

    ull acc[8][4] = {};

    const int nchunk = K >> 4;
    for (int kb = 0; kb < nchunk; kb++) {
        {   // load A tile: 128 rows x 16 floats (8 ull). 2 threads/row, 4 ull each.
            int row  = tid >> 1;
            const float* ga = A + (size_t)(m0 + row) * lda + kb * 16 + (tid & 1) * 8;
            ull* dst = &As[row * 9 + (tid & 1) * 4];
            #pragma unroll
            for (int q = 0; q < 4; q++) dst[q] = *(const ull*)(ga + q * 2);
        }
        if (tid < 128) {  // load W tile: 64 rows x 16 floats
            int rw = tid >> 1;
            const float* gb = W + (size_t)(n0 + rw) * HN + kb * 16 + (tid & 1) * 8;
            ull* db = &Bs[rw * 9 + (tid & 1) * 4];
            #pragma unroll
            for (int q = 0; q < 4; q++) db[q] = *(const ull*)(gb + q * 2);
        }
        __syncthreads();

        #pragma unroll
        for (int kp = 0; kp < 8; kp++) {
            ull b2[4];
            #pragma unroll
            for (int j = 0; j < 4; j++) b2[j] = Bs[(tx + 16 * j) * 9 + kp];
            #pragma unroll
            for (int i = 0; i < 8; i++) {
                ull a2 = As[(ty + 16 * i) * 9 + kp];
                #pragma unroll
                for (int j = 0; j < 4; j++) acc[i][j] = fma2(a2, b2[j], acc[i][j]);
            }
        }
        __syncthreads();
    }

    #pragma unroll
    for (int j = 0; j < 4; j++) {
        int n = n0 + tx + 16 * j;
        float bias = bih[n] + bhh[n];
        #pragma unroll
        for (int i = 0; i < 8; i++) {
            int m = m0 + ty + 16 * i;
            g_gx[(size_t)m * GN + n] = lo_f(acc[i][j]) + hi_f(acc[i][j]) + bias;
        }
    }
}

// ---------------- recurrent scan (one launch per layer) ----------------
// 16 clusters x 8 CTAs, 512 threads/CTA. Cluster c owns batch rows [8c,8c+8).
// CTA rank r owns hidden units [32r,32r+32) -> 128 gate rows of W_hh held
// ENTIRELY IN REGISTERS: thread (g2 = tid&63, kq = tid>>6) keeps gate rows
// {2g2, 2g2+1}, K-slice [32kq, 32kq+32) = 64 registers of weights.
// Per step (R14 protocol; R16 = R14 + 16B cp.async + v4 DSMEM stores):
//   - warps 0-7: 256 x 16B cp.async.cg prefetch of gx(t) into gxs
//   - mbarrier wait (count 64, phase parity): all peers' h(t-1) arrived
//   - matvec: register weights x broadcast-LDS h -> pre[8][8][128]
//   - __syncthreads
//   - stage2 (tid<256): reduce partials + gx, activations, c/h update; h quads
//     (16B) to all 8 CTAs via st.shared::cluster.v4.b32; per-warp
//     fence.acq_rel.cluster + remote plain mbarrier arrive (8 warps x 8 CTAs)
//   - __syncthreads
#define SCAN_H_F   4096                       // hbuf [2][8][256]
#define SCAN_P_F   8192                       // pre  [8 kq][8 row][128 gr]
#define SCAN_G_F   1024                       // gxs  [8 row][4 q][32 u]
#define SCAN_C_F   256                        // cst
#define SCAN_SMEM_FLOATS (SCAN_H_F + SCAN_P_F + SCAN_G_F + SCAN_C_F + 8)
#define SCAN_SMEM_BYTES  (SCAN_SMEM_FLOATS * 4)

__global__ void __cluster_dims__(CL, 1, 1) __launch_bounds__(512, 1)
lstm_scan(const float* __restrict__ whh,   // [GN][HN] for this layer
          const float* __restrict__ h0l,   // [BN][HN]
          const float* __restrict__ c0l,   // [BN][HN]
          int outIdx)
{
    extern __shared__ float sm[];
    float* hbuf = sm;                                   // [2][8][256]
    float* pre  = hbuf + SCAN_H_F;                      // [8][8][128]
    float* gxs  = pre + SCAN_P_F;                       // [8][4][32]
    float* cst  = gxs + SCAN_G_F;                       // [256]
    const unsigned mbar = smem_u32(cst + SCAN_C_F);     // 8B aligned
    const unsigned hbase = smem_u32(hbuf);
    const unsigned gxbase = smem_u32(gxs);

    const int tid   = threadIdx.x;
    const unsigned rank = cluster_rank();   // 0..7
    const int bb    = (blockIdx.x >> 3) * 8;            // first batch row

    const int g2  = tid & 63;               // gate-row pair
    const int kq  = tid >> 6;               // 0..7, warp-uniform
    const int row = tid >> 5, u = tid & 31; // stage-2 mapping (tid<256)
    const int gu  = rank * 32 + u;
    // gx loader mapping (tid<256): one 16B chunk per thread
    const int lrow = tid >> 5, lq = (tid >> 3) & 3, lseg = tid & 7;

    // ---- init mbarrier (count = 8 warps x 8 CTAs = 64 arrivals per step)
    if (tid == 0)
        asm volatile("mbarrier.init.shared.b64 [%0], %1;" :: "r"(mbar), "r"(64) : "memory");

    // ---- load this thread's W slice into REGISTERS (loop-invariant)
    ulonglong2 W0[8], W1[8];
    {
        int gr0 = 2 * g2,     q0 = gr0 >> 5, ul0 = gr0 & 31;
        int gr1 = 2 * g2 + 1, q1 = gr1 >> 5, ul1 = gr1 & 31;
        const float* w0p = whh + (size_t)(q0 * HN + rank * 32 + ul0) * HN + kq * 32;
        const float* w1p = whh + (size_t)(q1 * HN + rank * 32 + ul1) * HN + kq * 32;
        #pragma unroll
        for (int kk = 0; kk < 8; kk++) {
            W0[kk] = *(const ulonglong2*)(w0p + kk * 4);
            W1[kk] = *(const ulonglong2*)(w1p + kk * 4);
        }
    }

    // ---- init h (buffer 0), c
    for (int li = tid; li < 8 * HN; li += 512)
        hbuf[li] = h0l[(size_t)(bb + (li >> 8)) * HN + (li & 255)];
    if (tid < 256)
        cst[tid] = c0l[(size_t)(bb + row) * HN + gu];
    __syncthreads();
    // cluster sync: all mbarriers initialized before any remote arrive can land
    asm volatile("barrier.cluster.arrive.aligned;" ::: "memory");
    asm volatile("barrier.cluster.wait.aligned;"   ::: "memory");

    float* seq_out = g_act[outIdx];
    int ph = 0;                             // mbarrier phase parity

    for (int t = 0; t < TN; t++) {
        const int cur = t & 1, nxt = cur ^ 1;

        // ---- prefetch gx(t): 256 x 16B cp.async.cg (warps 0-7 only)
        if (tid < 256) {
            const float* g = g_gx + ((size_t)(bb + lrow) * TN + t) * GN
                           + lq * HN + rank * 32 + lseg * 4;
            unsigned d = gxbase + (unsigned)((lrow * 128 + lq * 32 + lseg * 4) * 4);
            cpa16(d, g);
            asm volatile("cp.async.commit_group;" ::: "memory");
        }

        // ---- wait for all peers' h(t-1) (64 arrivals); acquire cluster scope
        if (t) {
            unsigned done = 0;
            do {
                asm volatile(
                    "{\n\t.reg .pred P;\n\t"
                    "mbarrier.try_wait.parity.acquire.cluster.shared::cta.b64 P, [%1], %2, 0x989680;\n\t"
                    "selp.b32 %0, 1, 0, P;\n\t}"
                    : "=r"(done) : "r"(mbar), "r"(ph) : "memory");
            } while (!done);
            ph ^= 1;
        }

        // ---- matvec: register weights, broadcast h; two 4-row passes
        {
            const ulonglong2* hb = (const ulonglong2*)(hbuf + cur * 2048) + kq * 8;
            #pragma unroll
            for (int pass = 0; pass < 2; pass++) {
                ull a0[4] = {}, a1[4] = {};
                const ulonglong2* hp = hb + pass * 4 * 64;
                #pragma unroll
                for (int kk = 0; kk < 8; kk++) {
                    ulonglong2 w0 = W0[kk], w1 = W1[kk];
                    #pragma unroll
                    for (int r = 0; r < 4; r++) {
                        ulonglong2 h = hp[r * 64 + kk];   // warp-uniform broadcast
                        a0[r] = fma2(w0.x, h.x, a0[r]);
                        a0[r] = fma2(w0.y, h.y, a0[r]);
                        a1[r] = fma2(w1.x, h.x, a1[r]);
                        a1[r] = fma2(w1.y, h.y, a1[r]);
                    }
                }
                #pragma unroll
                for (int r = 0; r < 4; r++) {
                    float p0 = lo_f(a0[r]) + hi_f(a0[r]);
                    float p1 = lo_f(a1[r]) + hi_f(a1[r]);
                    ull pk = ((ull)__float_as_uint(p1) << 32) | (ull)__float_as_uint(p0);
                    *(ull*)&pre[(kq * 8 + pass * 4 + r) * 128 + 2 * g2] = pk;  // STS.64
                }
            }
        }
        __syncthreads();

        // ---- stage 2: reduce partials + activations + state + DSMEM broadcast
        if (tid < 256) {
            asm volatile("cp.async.wait_group 0;" ::: "memory");
            const float* gxr = gxs + row * 128;
            float gi = gxr[u], gf = gxr[32 + u], gg = gxr[64 + u], go = gxr[96 + u];
            #pragma unroll
            for (int p = 0; p < 8; p++) {
                const float* pr = pre + (p * 8 + row) * 128;
                gi += pr[u];
                gf += pr[32 + u];
                gg += pr[64 + u];
                go += pr[96 + u];
            }

            float c = sigm(gf) * cst[tid] + sigm(gi) * tanh_f(gg);
            float h = sigm(go) * tanh_f(c);

            // gather quads: lane u%4==0 stores (h_u..h_{u+3}) = 16B per CTA
            float hup = __shfl_down_sync(0xffffffffu, h, 1);
            ull hv = ((ull)__float_as_uint(hup) << 32) | (ull)__float_as_uint(h);
            ull hv2 = __shfl_down_sync(0xffffffffu, hv, 2);
            if ((tid & 3) == 0) {
                unsigned off = (unsigned)((nxt * 2048 + row * HN + gu) * 4);
                unsigned x0 = (unsigned)hv,  x1 = (unsigned)(hv  >> 32);
                unsigned x2 = (unsigned)hv2, x3 = (unsigned)(hv2 >> 32);
                #pragma unroll
                for (int d = 0; d < CL; d++) {
                    unsigned ra = mapa_u32(hbase, (unsigned)d) + off;
                    asm volatile("st.shared::cluster.v4.b32 [%0], {%1, %2, %3, %4};"
                                 :: "r"(ra), "r"(x0), "r"(x1), "r"(x2), "r"(x3) : "memory");
                }
            }
            __syncwarp();
            if ((tid & 31) == 0) {
                // publish this warp's stores cluster-wide, then arrive on all peers
                asm volatile("fence.acq_rel.cluster;" ::: "memory");
                #pragma unroll
                for (int d = 0; d < CL; d++) {
                    unsigned rb = mapa_u32(mbar, (unsigned)d);
                    asm volatile("mbarrier.arrive.shared::cluster.b64 _, [%0];"
                                 :: "r"(rb) : "memory");
                }
            }
            // off the cluster critical path:
            cst[tid] = c;
            seq_out[((size_t)(bb + row) * TN + t) * HN + gu] = h;
        }
        __syncthreads();   // protects pre + gxs for the next step
    }

    // exit safety: no CTA may leave while peers' remote stores could be in flight
    asm volatile("barrier.cluster.arrive.aligned;" ::: "memory");
    asm volatile("barrier.cluster.wait.aligned;"   ::: "memory");
}

// ---------------- final FC: out[b][o] = h_last[b] . fc_w[o] + fc_b[o] ----------------
__global__ void __launch_bounds__(256) fc_kernel(
    const float* __restrict__ fcw, const float* __restrict__ fcb,
    float* __restrict__ out)
{
    __shared__ float hs[HN];
    int b = blockIdx.x;
    const float* h = &g_act[(NL - 1) & 1][((size_t)b * TN + (TN - 1)) * HN];
    hs[threadIdx.x] = h[threadIdx.x];
    __syncthreads();
    if (threadIdx.x < ON) {
        int o = threadIdx.x;
        float s = fcb[o];
        #pragma unroll 8
        for (int u = 0; u < HN; u++) s += hs[u] * fcw[o * HN + u];
        out[b * ON + o] = s;
    }
}

// ---------------- launch ----------------
extern "C" void kernel_launch(void* const* d_in, const int* in_sizes, int n_in,
                              void* d_out, int out_size)
{
    (void)in_sizes; (void)n_in; (void)out_size;
    const float* x   = (const float*)d_in[0];
    const float* h0  = (const float*)d_in[1];
    const float* c0  = (const float*)d_in[2];
    const float* wih = (const float*)d_in[3];
    const float* whh = (const float*)d_in[4];
    const float* bih = (const float*)d_in[5];
    const float* bhh = (const float*)d_in[6];
    const float* fcw = (const float*)d_in[7];
    const float* fcb = (const float*)d_in[8];
    float* out = (float*)d_out;

    // idempotent, host-side, capture-safe
    cudaFuncSetAttribute(lstm_scan, cudaFuncAttributeMaxDynamicSharedMemorySize, SCAN_SMEM_BYTES);

    for (int l = 0; l < NL; l++) {
        const float* A = (l == 0) ? x : nullptr;
        int inIdx = (l == 0) ? 0 : ((l - 1) & 1);
        int lda   = (l == 0) ? IND : HN;
        dim3 grid(BN * TN / 128, GN / 64);
        gx_gemm<<<grid, 256>>>(A, inIdx, lda, lda,
                               wih + (size_t)l * GN * HN,
                               bih + (size_t)l * GN,
                               bhh + (size_t)l * GN);
        lstm_scan<<<128, 512, SCAN_SMEM_BYTES>>>(
            whh + (size_t)l * GN * HN,
            h0  + (size_t)l * BN * HN,
            c0  + (size_t)l * BN * HN,
            l & 1);
    }
    fc_kernel<<<BN, 256>>>(fcw, fcb, out);
}